// round 13
// baseline (speedup 1.0000x reference)
#include <cuda_runtime.h>
#include <cuda_bf16.h>

// Problem constants (fixed by the reference): B=256, T=2048, L=4, H=64, P=1.
#define BSZ   256
#define TLEN  2048
#define NLAY  4
#define HID   64
#define CHUNK 32          // timesteps per BSP iteration (= warp width)
#define NCH   (TLEN/CHUNK)

#define L2E 1.4426950408889634f   // log2(e)

__device__ __forceinline__ float ex2(float x) {
    float r; asm("ex2.approx.ftz.f32 %0, %1;" : "=f"(r) : "f"(x)); return r;
}
__device__ __forceinline__ float rcpa(float x) {
    float r; asm("rcp.approx.ftz.f32 %0, %1;" : "=f"(r) : "f"(x)); return r;
}
__device__ __forceinline__ float tanha(float x) {
    float r; asm("tanh.approx.f32 %0, %1;" : "=f"(r) : "f"(x)); return r;
}

// Per-layer, per-lane register weights.
// Gates i,f,o use sigm(x) = 0.5 + 0.5*tanh(x/2): the /2 is folded into wi/wh/bs.
// Gate g uses tanh directly (no fold). wr is pre-halved (0.5*wr) so
// ow = wr*sigm(o-arg) = fma(t_o, wrh, wrh).
// j layout: j = gate*2 + part; gate 0:i 1:f 2:g 3:o; part 0 -> cell ln, 1 -> cell ln+32.
struct Lw { float wi[8], wh[8], bs[8], wrh0, wrh1; };

__device__ __forceinline__ void load_layer(
    Lw& L, int l, int ln,
    const float* __restrict__ Wih, const float* __restrict__ Whh,
    const float* __restrict__ bih, const float* __restrict__ bhh,
    const float* __restrict__ Whr)
{
    const float* wih_l = Wih + l * 4 * HID;
    const float* whh_l = Whh + l * 4 * HID;
    const float* bih_l = bih + l * 4 * HID;
    const float* bhh_l = bhh + l * 4 * HID;
#pragma unroll
    for (int j = 0; j < 8; ++j) {
        int gate = j >> 1;
        int idx  = gate * 64 + ln + (j & 1) * 32;
        float s  = (gate == 2) ? 1.0f : 0.5f;      // sigmoid gates: arg/2
        L.wi[j] = s * wih_l[idx];
        L.wh[j] = s * whh_l[idx];
        L.bs[j] = s * (bih_l[idx] + bhh_l[idx]);
    }
    L.wrh0 = 0.5f * Whr[l * HID + ln];
    L.wrh1 = 0.5f * Whr[l * HID + ln + 32];
}

// Fused dual LSTM step: two independent layer-chains (A, B) hand-interleaved
// so B's issue fills A's latency bubbles and the two butterflies pipeline.
// Cell state is kept pre-scaled: cs = -2*L2E*c, so tanh(c) = (1-2^cs)/(1+2^cs)
// with ex2 consuming cs directly. i enters c as -2*L2E*sigm(i) = fma(t_i,-L2E,-L2E).
__device__ __forceinline__ void dual_step(
    const Lw& A, const Lw& B, float xa, float xbv,
    float& hA, float& cA0, float& cA1,
    float& hB, float& cB0, float& cB1)
{
    // ---- gate pre-activations (1 chain-FMA each; xb computed off-chain) ----
    float aA[8], aB[8];
#pragma unroll
    for (int j = 0; j < 8; ++j) aA[j] = fmaf(hA, A.wh[j], fmaf(xa,  A.wi[j], A.bs[j]));
#pragma unroll
    for (int j = 0; j < 8; ++j) aB[j] = fmaf(hB, B.wh[j], fmaf(xbv, B.wi[j], B.bs[j]));

    // ---- 16 tanh.approx, A first (its chain continues while B's issue) ----
    float tA[8], tB[8];
#pragma unroll
    for (int j = 0; j < 8; ++j) tA[j] = tanha(aA[j]);
#pragma unroll
    for (int j = 0; j < 8; ++j) tB[j] = tanha(aB[j]);

    // ---- gates: i2 = -2*L2E*sigm(i); f = sigm(f); tg = tanh(g); ow = wr*sigm(o) ----
    float i2A0 = fmaf(tA[0], -L2E, -L2E), i2A1 = fmaf(tA[1], -L2E, -L2E);
    float fA0  = fmaf(tA[2], 0.5f, 0.5f), fA1  = fmaf(tA[3], 0.5f, 0.5f);
    float owA0 = fmaf(tA[6], A.wrh0, A.wrh0), owA1 = fmaf(tA[7], A.wrh1, A.wrh1);
    float i2B0 = fmaf(tB[0], -L2E, -L2E), i2B1 = fmaf(tB[1], -L2E, -L2E);
    float fB0  = fmaf(tB[2], 0.5f, 0.5f), fB1  = fmaf(tB[3], 0.5f, 0.5f);
    float owB0 = fmaf(tB[6], B.wrh0, B.wrh0), owB1 = fmaf(tB[7], B.wrh1, B.wrh1);

    // ---- cell update in pre-scaled space: cs' = f*cs + i2*tg ----
    cA0 = fmaf(fA0, cA0, i2A0 * tA[4]);
    cA1 = fmaf(fA1, cA1, i2A1 * tA[5]);
    cB0 = fmaf(fB0, cB0, i2B0 * tB[4]);
    cB1 = fmaf(fB1, cB1, i2B1 * tB[5]);

    // ---- exact tanh(c): ec = 2^cs (clamped), tc = (1-ec)/(1+ec) ----
    float eA0 = ex2(fminf(cA0, 28.0f)), eA1 = ex2(fminf(cA1, 28.0f));
    float eB0 = ex2(fminf(cB0, 28.0f)), eB1 = ex2(fminf(cB1, 28.0f));
    float tcA0 = (1.0f - eA0) * rcpa(1.0f + eA0);
    float tcA1 = (1.0f - eA1) * rcpa(1.0f + eA1);
    float tcB0 = (1.0f - eB0) * rcpa(1.0f + eB0);
    float tcB1 = (1.0f - eB1) * rcpa(1.0f + eB1);

    // ---- projection partials ----
    float pA = fmaf(owA0, tcA0, owA1 * tcA1);
    float pB = fmaf(owB0, tcB0, owB1 * tcB1);

    // ---- interleaved 5-hop butterflies (hops pipeline in MIO) ----
#pragma unroll
    for (int m = 16; m >= 1; m >>= 1) {
        float sA = __shfl_xor_sync(0xffffffffu, pA, m);
        float sB = __shfl_xor_sync(0xffffffffu, pB, m);
        pA += sA;
        pB += sB;
    }
    hA = pA;
    hB = pB;
}

// One block per batch element, 2 warps. Warp w runs layers {2w, 2w+1} as two
// interleaved wavefront chains (layer l processes chunk it-l at iteration it).
// 0->1 and 2->3 handoffs are intra-warp registers; 1->2 via double-buffered
// smem ring + one __syncthreads per iteration. Max 1 warp per SMSP chip-wide.
__global__ __launch_bounds__(64) void lstm_dual_kernel(
    const float* __restrict__ y,     // [B, T, 1]
    const float* __restrict__ Wih,   // [L, 256, 1]
    const float* __restrict__ Whh,   // [L, 256, 1]
    const float* __restrict__ bih,   // [L, 256]
    const float* __restrict__ bhh,   // [L, 256]
    const float* __restrict__ Whr,   // [L, 1, 64]
    const int*   __restrict__ mslp,
    float*       __restrict__ out)   // [B, T-msl, 1]
{
    __shared__ float ring_s[2][CHUNK];

    const int b  = blockIdx.x;
    const int w  = threadIdx.x >> 5;   // warp 0 -> layers 0,1; warp 1 -> layers 2,3
    const int ln = threadIdx.x & 31;

    Lw A, B;
    load_layer(A, 2 * w,     ln, Wih, Whh, bih, bhh, Whr);
    load_layer(B, 2 * w + 1, ln, Wih, Whh, bih, bhh, Whr);

    const int   msl = *mslp;
    const int   To  = TLEN - msl;
    const float* yb = y + b * TLEN;

    float hA = 0.f, cA0 = 0.f, cA1 = 0.f;
    float hB = 0.f, cB0 = 0.f, cB1 = 0.f;
    float keepA = 0.f;                       // chain A's chunk from previous iteration
    float xpre  = (w == 0) ? yb[ln] : 0.f;   // prefetch chunk 0 for layer 0

    const int NIT = NCH + NLAY - 1;          // 67 wavefront iterations
    for (int it = 0; it < NIT; ++it) {
        // ---- inputs ----
        float xB = keepA;                    // layer (2w+1) chunk it-(2w+1) = A's prev output
        float xA;
        if (w == 0) {
            xA   = xpre;
            xpre = (it + 1 < NCH) ? yb[(it + 1) * CHUNK + ln] : 0.f;  // off-chain
        } else {
            xA = ring_s[(it + 1) & 1][ln];   // layer1 chunk it-2, written at it-1
        }

        // ---- state reset at each chain's first real chunk ----
        if (it == 2 * w)     { hA = 0.f; cA0 = 0.f; cA1 = 0.f; }
        if (it == 2 * w + 1) { hB = 0.f; cB0 = 0.f; cB1 = 0.f; }

        // ---- 32 fused dual steps ----
        float keepAn = 0.f, keepBn = 0.f;
#pragma unroll 4
        for (int tt = 0; tt < CHUNK; ++tt) {
            float xa = __shfl_sync(0xffffffffu, xA, tt);
            float xb = __shfl_sync(0xffffffffu, xB, tt);
            dual_step(A, B, xa, xb, hA, cA0, cA1, hB, cB0, cB1);
            keepAn = (tt == ln) ? hA : keepAn;
            keepBn = (tt == ln) ? hB : keepBn;
        }
        keepA = keepAn;

        // ---- publish ----
        if (w == 0) {
            ring_s[it & 1][ln] = keepBn;                  // layer1 chunk it-1 -> layer2
        } else if (it >= 3) {
            int t = (it - 3) * CHUNK + ln;                // layer3 chunk it-3
            if (t >= msl) out[b * To + (t - msl)] = keepBn;
        }

        __syncthreads();   // RAW+WAR for the double-buffered ring (2 warps, cheap)
    }
}

extern "C" void kernel_launch(void* const* d_in, const int* in_sizes, int n_in,
                              void* d_out, int out_size) {
    const float* y    = (const float*)d_in[0];
    const float* Wih  = (const float*)d_in[1];
    const float* Whh  = (const float*)d_in[2];
    const float* bih  = (const float*)d_in[3];
    const float* bhh  = (const float*)d_in[4];
    const float* Whr  = (const float*)d_in[5];
    const int*   msl  = (const int*)  d_in[6];
    float* out = (float*)d_out;
    (void)in_sizes; (void)n_in; (void)out_size;

    lstm_dual_kernel<<<BSZ, 64>>>(y, Wih, Whh, bih, bhh, Whr, msl, out);
}

// round 14
// speedup vs baseline: 2.0846x; 2.0846x over previous
#include <cuda_runtime.h>
#include <cuda_bf16.h>

// Problem constants (fixed by the reference): B=256, T=2048, L=4, H=64, P=1.
#define BSZ   256
#define TLEN  2048
#define NLAY  4
#define HID   64
#define CHUNK 32          // timesteps per BSP iteration (= warp width)
#define NCH   (TLEN/CHUNK)

#define L2E   1.4426950408889634f     // log2(e)
#define FXS   16777216.0f             // 2^24  fixed-point scale (folded into wr)
#define FXI   5.9604644775390625e-8f  // 2^-24 descale (folded into wh / outputs)

__device__ __forceinline__ float ex2(float x) {
    float r; asm("ex2.approx.ftz.f32 %0, %1;" : "=f"(r) : "f"(x)); return r;
}
__device__ __forceinline__ float rcpa(float x) {
    float r; asm("rcp.approx.ftz.f32 %0, %1;" : "=f"(r) : "f"(x)); return r;
}
// Integer warp allreduce — single instruction on sm_103 (f32 variant doesn't exist).
__device__ __forceinline__ int redux_add(int v) {
    int r; asm volatile("redux.sync.add.s32 %0, %1, 0xffffffff;" : "=r"(r) : "r"(v));
    return r;
}

// One block per batch element; warp w == layer w (BSP wavefront over chunks).
// Lane ln owns cells {ln, ln+32}; torch gate order i, f, g, o.
// Weights pre-scaled so the gate FMA directly yields the EX2 argument:
//   sigm gates (i,f,o): a = -L2E*g   -> sigm = 1/(1+2^a)
//   tanh gate  (g):     a = -2L2E*g  -> tanh = (1-2^a)/(1+2^a)
// Fixed-point h: wr *= 2^24 so the projection partial is integer-scaled;
// allreduce via F2I + redux.sync.add.s32 + I2F; wh *= 2^-24 absorbs the descale.
// All 8 gate denominators share ONE rcp (Montgomery tree); tanh(c) pair shares one.
__global__ __launch_bounds__(128) void lstm_bsp_kernel(
    const float* __restrict__ y,     // [B, T, 1]
    const float* __restrict__ Wih,   // [L, 256, 1]
    const float* __restrict__ Whh,   // [L, 256, 1]
    const float* __restrict__ bih,   // [L, 256]
    const float* __restrict__ bhh,   // [L, 256]
    const float* __restrict__ Whr,   // [L, 1, 64]
    const int*   __restrict__ mslp,
    float*       __restrict__ out)   // [B, T-msl, 1]
{
    __shared__ float ring_s[NLAY - 1][2][CHUNK];

    const int b  = blockIdx.x;
    const int l  = threadIdx.x >> 5;   // layer == warp id (one per SMSP)
    const int ln = threadIdx.x & 31;

    // ---- per-lane weights, pre-scaled, register resident ----
    float wi[8], wh[8], bs[8];
    {
        const float* wih_l = Wih + l * 4 * HID;
        const float* whh_l = Whh + l * 4 * HID;
        const float* bih_l = bih + l * 4 * HID;
        const float* bhh_l = bhh + l * 4 * HID;
#pragma unroll
        for (int j = 0; j < 8; ++j) {
            int gate = j >> 1;                      // 0:i 1:f 2:g 3:o
            int idx  = gate * 64 + ln + (j & 1) * 32;
            float s  = (gate == 2) ? (-2.0f * L2E) : (-L2E);
            wi[j] = s * wih_l[idx];
            wh[j] = s * whh_l[idx] * FXI;           // consumes integer-valued h directly
            bs[j] = s * (bih_l[idx] + bhh_l[idx]);
        }
    }
    const float wr0 = Whr[l * HID + ln]      * FXS;  // partial pre-scaled to fixed point
    const float wr1 = Whr[l * HID + ln + 32] * FXS;

    const int   msl = *mslp;
    const int   To  = TLEN - msl;
    const float* yb = y + b * TLEN;

    float h = 0.0f;            // integer-valued float: actual hidden = h * 2^-24
    float c0 = 0.0f, c1 = 0.0f;
    float xpre = (l == 0) ? yb[ln] : 0.0f;   // prefetch chunk 0 for layer 0

    const int NIT = NCH + NLAY - 1;          // 67 wavefront iterations
    for (int it = 0; it < NIT; ++it) {
        const int nc  = it - l;
        const bool act = ((unsigned)nc < (unsigned)NCH);

        if (act) {
            // ---- obtain input chunk (real scale) ----
            float xcur;
            if (l == 0) {
                xcur = xpre;
                xpre = (nc + 1 < NCH) ? yb[(nc + 1) * CHUNK + ln] : 0.0f; // off-chain prefetch
            } else {
                xcur = ring_s[l - 1][(it - 1) & 1][ln];  // produced at iteration it-1
            }

            // ---- 32 recurrence steps ----
            float keep = 0.0f;
#pragma unroll 8
            for (int tt = 0; tt < CHUNK; ++tt) {
                float x = __shfl_sync(0xffffffffu, xcur, tt);   // off the h-chain

                // xb depends only on x -> off the h-critical-path
                float xb[8], e[8], d[8];
#pragma unroll
                for (int j = 0; j < 8; ++j) xb[j] = fmaf(x, wi[j], bs[j]);
#pragma unroll
                for (int j = 0; j < 8; ++j) {
                    float a = fmaf(h, wh[j], xb[j]);            // 1 FMA on chain
                    a = fminf(a, 14.0f);   // keep 8-product < 2^128 (inf poisons batch)
                    e[j] = ex2(a);
                    d[j] = 1.0f + e[j];
                }

                // ---- Montgomery batched reciprocal of the 8 denominators ----
                float p01 = d[0] * d[1], p23 = d[2] * d[3];
                float p45 = d[4] * d[5], p67 = d[6] * d[7];
                float pA  = p01 * p23,   pB  = p45 * p67;
                float r   = rcpa(pA * pB);                      // ONE rcp for 8
                float rA  = r * pB,      rB2 = r * pA;
                float r01 = rA * p23,    r23 = rA * p01;
                float r45 = rB2 * p67,   r67 = rB2 * p45;
                float i0 = r01 * d[1],   i1 = r01 * d[0];       // sigm(i)
                float f0 = r23 * d[3],   f1 = r23 * d[2];       // sigm(f)
                float g0 = r45 * d[5],   g1 = r45 * d[4];       // 1/(1+e) for tanh(g)
                float o0 = r67 * d[7],   o1 = r67 * d[6];       // sigm(o)

                float tg0 = (1.0f - e[4]) * g0;                 // tanh(g)
                float tg1 = (1.0f - e[5]) * g1;

                c0 = fmaf(f0, c0, i0 * tg0);
                c1 = fmaf(f1, c1, i1 * tg1);

                float ow0 = o0 * wr0, ow1 = o1 * wr1;           // off-chain vs tanh(c)

                // tanh(c): shared rcp for both denominators
                float ac0 = fminf(c0 * (-2.0f * L2E), 14.0f);
                float ac1 = fminf(c1 * (-2.0f * L2E), 14.0f);
                float ec0 = ex2(ac0), ec1 = ex2(ac1);
                float dc0 = 1.0f + ec0, dc1 = 1.0f + ec1;
                float rc  = rcpa(dc0 * dc1);                    // ONE rcp for 2
                float tc0 = (1.0f - ec0) * (rc * dc1);
                float tc1 = (1.0f - ec1) * (rc * dc0);

                // ---- fixed-point 64-wide allreduce: F2I + REDUX + I2F ----
                float part = fmaf(ow0, tc0, ow1 * tc1);         // already * 2^24
                int   pi   = __float2int_rn(part);
                h = (float)redux_add(pi);                       // integer-valued float

                keep = (tt == ln) ? h : keep;                   // stage for coalesced emit
            }

            // ---- publish chunk (convert back to real scale once per chunk) ----
            if (l < NLAY - 1) {
                ring_s[l][it & 1][ln] = keep * FXI;
            } else {
                int t = nc * CHUNK + ln;
                if (t >= msl) out[b * To + (t - msl)] = keep * FXI;
            }
        }

        __syncthreads();   // single barrier: RAW + WAR for the double buffer
    }
}

extern "C" void kernel_launch(void* const* d_in, const int* in_sizes, int n_in,
                              void* d_out, int out_size) {
    const float* y    = (const float*)d_in[0];
    const float* Wih  = (const float*)d_in[1];
    const float* Whh  = (const float*)d_in[2];
    const float* bih  = (const float*)d_in[3];
    const float* bhh  = (const float*)d_in[4];
    const float* Whr  = (const float*)d_in[5];
    const int*   msl  = (const int*)  d_in[6];
    float* out = (float*)d_out;
    (void)in_sizes; (void)n_in; (void)out_size;

    lstm_bsp_kernel<<<BSZ, 128>>>(y, Wih, Whh, bih, bhh, Whr, msl, out);
}

// round 15
// speedup vs baseline: 2.1784x; 1.0450x over previous
#include <cuda_runtime.h>
#include <cuda_bf16.h>

// Problem constants (fixed by the reference): B=256, T=2048, L=4, H=64, P=1.
#define BSZ   256
#define TLEN  2048
#define NLAY  4
#define HID   64
#define CHUNK 32          // timesteps per BSP iteration (= warp width)
#define NCH   (TLEN/CHUNK)

#define L2E   1.4426950408889634f   // log2(e)
#define FXS   524288.0f             // 2^19 fixed-point scale (folded into wr)
#define FXI   1.9073486328125e-6f   // 2^-19 descale (folded into wh / outputs)
#define MAGIC 12582912.0f           // 1.5 * 2^23 : float->int round trick
#define MAGICB 0x4B400000

typedef unsigned long long ull;     // packed f32x2

__device__ __forceinline__ float ex2(float x) {
    float r; asm("ex2.approx.ftz.f32 %0, %1;" : "=f"(r) : "f"(x)); return r;
}
__device__ __forceinline__ float rcpa(float x) {
    float r; asm("rcp.approx.ftz.f32 %0, %1;" : "=f"(r) : "f"(x)); return r;
}
__device__ __forceinline__ int redux_add(int v) {
    int r; asm volatile("redux.sync.add.s32 %0, %1, 0xffffffff;" : "=r"(r) : "r"(v));
    return r;
}
// ---- f32x2 packed ops (FFMA2/FMUL2/FADD2 — PTX-only on sm_103a) ----
__device__ __forceinline__ ull pk(float lo, float hi) {
    ull r; asm("mov.b64 %0, {%1, %2};" : "=l"(r) : "f"(lo), "f"(hi)); return r;
}
__device__ __forceinline__ void upk(float& lo, float& hi, ull v) {
    asm("mov.b64 {%0, %1}, %2;" : "=f"(lo), "=f"(hi) : "l"(v));
}
__device__ __forceinline__ ull fma2(ull a, ull b, ull c) {
    ull r; asm("fma.rn.f32x2 %0, %1, %2, %3;" : "=l"(r) : "l"(a), "l"(b), "l"(c)); return r;
}
__device__ __forceinline__ ull mul2(ull a, ull b) {
    ull r; asm("mul.rn.f32x2 %0, %1, %2;" : "=l"(r) : "l"(a), "l"(b)); return r;
}
__device__ __forceinline__ ull add2(ull a, ull b) {
    ull r; asm("add.rn.f32x2 %0, %1, %2;" : "=l"(r) : "l"(a), "l"(b)); return r;
}

// One block per batch element; warp w == layer w (BSP wavefront over chunks).
// Lane ln owns cells {ln, ln+32}: all per-gate values packed f32x2 (part0,part1).
// Weights pre-scaled so the gate FMA2 directly yields the EX2 argument:
//   sigm gates (i,f,o): a = -L2E*g   -> sigm = 1/(1+2^a)
//   tanh gate  (g):     a = -2L2E*g  -> tanh = (1-2^a)/(1+2^a)
// Vertical Montgomery tree: P_part = prod of 4 gate denoms per part; 2 rcps.
// Fixed-point h (2^19) + magic-number round + redux.sync.add.s32 allreduce.
__global__ __launch_bounds__(128) void lstm_bsp_kernel(
    const float* __restrict__ y,     // [B, T, 1]
    const float* __restrict__ Wih,   // [L, 256, 1]
    const float* __restrict__ Whh,   // [L, 256, 1]
    const float* __restrict__ bih,   // [L, 256]
    const float* __restrict__ bhh,   // [L, 256]
    const float* __restrict__ Whr,   // [L, 1, 64]
    const int*   __restrict__ mslp,
    float*       __restrict__ out)   // [B, T-msl, 1]
{
    __shared__ float ring_s[NLAY - 1][2][CHUNK];

    const int b  = blockIdx.x;
    const int l  = threadIdx.x >> 5;   // layer == warp id
    const int ln = threadIdx.x & 31;

    // ---- packed per-lane weights: wX2[gate] = (part0, part1) ----
    ull wi2[4], wh2[4], bs2[4];
    {
        const float* wih_l = Wih + l * 4 * HID;
        const float* whh_l = Whh + l * 4 * HID;
        const float* bih_l = bih + l * 4 * HID;
        const float* bhh_l = bhh + l * 4 * HID;
#pragma unroll
        for (int g = 0; g < 4; ++g) {           // 0:i 1:f 2:g 3:o
            float s = (g == 2) ? (-2.0f * L2E) : (-L2E);
            int i0 = g * 64 + ln, i1 = i0 + 32;
            wi2[g] = pk(s * wih_l[i0], s * wih_l[i1]);
            wh2[g] = pk(s * whh_l[i0] * FXI, s * whh_l[i1] * FXI); // eats int-valued h
            bs2[g] = pk(s * (bih_l[i0] + bhh_l[i0]), s * (bih_l[i1] + bhh_l[i1]));
        }
    }
    const ull wr2 = pk(Whr[l * HID + ln] * FXS, Whr[l * HID + ln + 32] * FXS);

    const ull ones2 = pk(1.0f, 1.0f);
    const ull neg12 = pk(-1.0f, -1.0f);
    const ull nl2e2 = pk(-2.0f * L2E, -2.0f * L2E);

    const int   msl = *mslp;
    const int   To  = TLEN - msl;
    const float* yb = y + b * TLEN;

    float hf = 0.0f;               // integer-valued float: real h = hf * 2^-19
    ull c2 = pk(0.0f, 0.0f);       // cell state (real scale), packed
    float xpre = (l == 0) ? yb[ln] : 0.0f;

    const int NIT = NCH + NLAY - 1;          // 67 wavefront iterations
    for (int it = 0; it < NIT; ++it) {
        const int nc  = it - l;
        const bool act = ((unsigned)nc < (unsigned)NCH);

        if (act) {
            float xcur;
            if (l == 0) {
                xcur = xpre;
                xpre = (nc + 1 < NCH) ? yb[(nc + 1) * CHUNK + ln] : 0.0f;
            } else {
                xcur = ring_s[l - 1][(it - 1) & 1][ln];
            }

            float keep = 0.0f;
#pragma unroll 8
            for (int tt = 0; tt < CHUNK; ++tt) {
                float x = __shfl_sync(0xffffffffu, xcur, tt);
                ull x2 = pk(x, x);
                ull h2 = pk(hf, hf);

                // ---- gate args + ex2 + denominators, packed per gate ----
                ull e2[4], d2[4];
#pragma unroll
                for (int g = 0; g < 4; ++g) {
                    ull xb = fma2(x2, wi2[g], bs2[g]);     // off-chain
                    ull a2 = fma2(h2, wh2[g], xb);         // 1 FFMA2 on chain
                    float a0, a1; upk(a0, a1, a2);
                    a0 = fminf(a0, 28.0f);                 // 4-prod < 2^116, inf-safe
                    a1 = fminf(a1, 28.0f);                 // (FMNMX -> alu pipe)
                    e2[g] = pk(ex2(a0), ex2(a1));
                    d2[g] = add2(e2[g], ones2);
                }

                // ---- vertical Montgomery: 2 rcps serve all 8 denominators ----
                ull m1 = mul2(d2[0], d2[1]);               // (di*df) per part
                ull m2 = mul2(d2[2], d2[3]);               // (dg*do) per part
                ull m3 = mul2(m1, m2);                     // (P0, P1)
                float P0, P1; upk(P0, P1, m3);
                ull r2 = pk(rcpa(P0), rcpa(P1));
                ull t  = mul2(r2, m2);                     // 1/(di*df)
                ull u  = mul2(r2, m1);                     // 1/(dg*do)
                ull gi = mul2(t, d2[1]);                   // sigm(i) = 1/di
                ull gf = mul2(t, d2[0]);                   // sigm(f)
                ull vg = mul2(u, d2[3]);                   // 1/dg
                ull go = mul2(u, d2[2]);                   // sigm(o)

                ull tg = mul2(fma2(e2[2], neg12, ones2), vg);  // tanh(g)

                // ---- cell update (packed) ----
                c2 = fma2(gf, c2, mul2(gi, tg));

                ull ow = mul2(go, wr2);                    // off-chain vs tanh(c)

                // ---- tanh(c): packed ex2 + 2 rcps ----
                ull ac2 = mul2(c2, nl2e2);
                float a0, a1; upk(a0, a1, ac2);
                a0 = fminf(a0, 28.0f); a1 = fminf(a1, 28.0f);
                ull ec2 = pk(ex2(a0), ex2(a1));
                ull dc2 = add2(ec2, ones2);
                float q0, q1; upk(q0, q1, dc2);
                ull rc2 = pk(rcpa(q0), rcpa(q1));
                ull tc2 = mul2(fma2(ec2, neg12, ones2), rc2);

                // ---- projection partial + fixed-point allreduce ----
                ull pt = mul2(ow, tc2);                    // already * 2^19
                float p0, p1; upk(p0, p1, pt);
                float part = p0 + p1;
                float fm = part + MAGIC;                   // round-to-int in mantissa
                int   pi = __float_as_int(fm) - MAGICB;
                int   s  = redux_add(pi);
                hf = __int_as_float(s + MAGICB) - MAGIC;   // exact float(s), |s|<2^22

                keep = (tt == ln) ? hf : keep;
            }

            // ---- publish chunk (back to real scale once per chunk) ----
            if (l < NLAY - 1) {
                ring_s[l][it & 1][ln] = keep * FXI;
            } else {
                int t = nc * CHUNK + ln;
                if (t >= msl) out[b * To + (t - msl)] = keep * FXI;
            }
        }

        __syncthreads();   // single barrier: RAW + WAR for the double buffer
    }
}

extern "C" void kernel_launch(void* const* d_in, const int* in_sizes, int n_in,
                              void* d_out, int out_size) {
    const float* y    = (const float*)d_in[0];
    const float* Wih  = (const float*)d_in[1];
    const float* Whh  = (const float*)d_in[2];
    const float* bih  = (const float*)d_in[3];
    const float* bhh  = (const float*)d_in[4];
    const float* Whr  = (const float*)d_in[5];
    const int*   msl  = (const int*)  d_in[6];
    float* out = (float*)d_out;
    (void)in_sizes; (void)n_in; (void)out_size;

    lstm_bsp_kernel<<<BSZ, 128>>>(y, Wih, Whh, bih, bhh, Whr, msl, out);
}